// round 17
// baseline (speedup 1.0000x reference)
#include <cuda_runtime.h>
#include <cuda_fp16.h>
#include <cstdint>

#define TOKENS   16384
#define HIDDEN   4096
#define EXPERTS  64

#define M_TILE   128
#define NCTAS    (TOKENS / M_TILE)        // 128
#define KC       128
#define NITER    (HIDDEN / KC)            // 32
#define NTHREADS 512
#define NSTAGE   3

// ---- shared memory layout ----
// per stage: A 32KB (256 sub-rows x 128B; sub-row 2r+h = row r, k-half h)
//            B 16KB (128 sub-rows x 128B)
#define A_TILE_BYTES 32768
#define B_TILE_BYTES 16384
#define STG_BYTES    (A_TILE_BYTES + B_TILE_BYTES)   // 49152
#define B_OFF        A_TILE_BYTES
#define SM_MBAR   8
#define SM_SCALES 256
#define SM_STG    1024
#define SM_RED    (SM_STG + NSTAGE * STG_BYTES)      // 148480
#define SM_TOTAL  (SM_RED + 32768)                   // 181248

// SW128 swizzle (Swizzle<3,4,3>), applied within 128B sub-rows
#define SW(o) ((o) ^ (((o) >> 3) & 0x70))

// weights as fp16 (int8 values exact in fp16; scale folded into epilogue)
__device__ __half g_wh[EXPERTS * HIDDEN];

// ---------------- helpers ----------------
__device__ __forceinline__ uint32_t smem_to_u32(const void* p) {
    uint32_t a;
    asm("{ .reg .u64 t; cvta.to.shared.u64 t, %1; cvt.u32.u64 %0, t; }" : "=r"(a) : "l"(p));
    return a;
}
__device__ __forceinline__ void sts64(uint32_t addr, uint32_t a, uint32_t b) {
    asm volatile("st.shared.v2.b32 [%0], {%1,%2};" :: "r"(addr), "r"(a), "r"(b) : "memory");
}
__device__ __forceinline__ void sts128(uint32_t addr, uint32_t a, uint32_t b,
                                       uint32_t c, uint32_t d) {
    asm volatile("st.shared.v4.b32 [%0], {%1,%2,%3,%4};"
                 :: "r"(addr), "r"(a), "r"(b), "r"(c), "r"(d) : "memory");
}
__device__ __forceinline__ void lds128f(float (&v)[4], uint32_t addr) {
    asm volatile("ld.shared.v4.f32 {%0,%1,%2,%3}, [%4];"
                 : "=f"(v[0]), "=f"(v[1]), "=f"(v[2]), "=f"(v[3]) : "r"(addr));
}
// pack_f16(lo, hi): low half-word = f16(lo), high = f16(hi)
__device__ __forceinline__ uint32_t pack_f16(float lo, float hi) {
    uint32_t r;
    asm("cvt.rn.f16x2.f32 %0, %1, %2;" : "=r"(r) : "f"(hi), "f"(lo));
    return r;
}
__device__ __forceinline__ void ldsm4(uint32_t (&r)[4], uint32_t addr) {
    asm volatile("ldmatrix.sync.aligned.m8n8.x4.shared.b16 {%0,%1,%2,%3}, [%4];"
                 : "=r"(r[0]), "=r"(r[1]), "=r"(r[2]), "=r"(r[3]) : "r"(addr));
}
__device__ __forceinline__ void mma16816(float (&d)[4], const uint32_t (&a)[4],
                                         uint32_t b0, uint32_t b1) {
    asm volatile("mma.sync.aligned.m16n8k16.row.col.f32.f16.f16.f32 "
                 "{%0,%1,%2,%3}, {%4,%5,%6,%7}, {%8,%9}, {%0,%1,%2,%3};"
                 : "+f"(d[0]), "+f"(d[1]), "+f"(d[2]), "+f"(d[3])
                 : "r"(a[0]), "r"(a[1]), "r"(a[2]), "r"(a[3]), "r"(b0), "r"(b1));
}

#define MBARRIER_INIT(mbar, count) \
    asm volatile("mbarrier.init.shared.b64 [%0], %1;" \
                 :: "r"((uint32_t)(mbar)), "r"((uint32_t)(count)) : "memory")
#define MBARRIER_ARRIVE(mbar) \
    asm volatile("mbarrier.arrive.shared.b64 _, [%0];" :: "r"((uint32_t)(mbar)) : "memory")
#define MBARRIER_WAIT_PARITY(mbar_smem_addr, phase_parity) do { \
    uint32_t _mbar = (uint32_t)(mbar_smem_addr); \
    uint32_t _parity = (uint32_t)(phase_parity); \
    uint32_t _done; \
    asm volatile("{\n\t.reg .pred p;\n\t" \
        "mbarrier.try_wait.parity.shared.b64 p, [%1], %2;\n\t" \
        "selp.b32 %0, 1, 0, p;\n\t}" \
        : "=r"(_done) : "r"(_mbar), "r"(_parity) : "memory"); \
    if (!_done) { \
        asm volatile("{\n\t.reg .pred P1;\n\t" \
            "WAIT_LOOP_%=:\n\t" \
            "mbarrier.try_wait.parity.shared.b64 P1, [%0], %1, 0x989680;\n\t" \
            "@P1 bra.uni WAIT_DONE_%=;\n\t" \
            "bra.uni WAIT_LOOP_%=;\n\t" \
            "WAIT_DONE_%=:\n\t}" \
            :: "r"(_mbar), "r"(_parity) : "memory"); \
    } \
} while (0)

// ---------------- kernels ----------------

__global__ void dequant_kernel(const int* __restrict__ w) {
    int t = blockIdx.x * blockDim.x + threadIdx.x;        // 0..65535, 4 weights each
    int4 v = ((const int4*)w)[t];
    uint2 p;
    p.x = pack_f16((float)v.x, (float)v.y);
    p.y = pack_f16((float)v.z, (float)v.w);
    ((uint2*)g_wh)[t] = p;
}

__global__ void __launch_bounds__(NTHREADS, 1)
gemm_kernel(const float* __restrict__ x,
            const float* __restrict__ scales,
            float* __restrict__ out) {
    extern __shared__ char smem[];
    const uint32_t sbase = smem_to_u32(smem);
    const int tid = threadIdx.x;
    const int wid = tid >> 5;
    const int lid = tid & 31;
    const int m0  = blockIdx.x * M_TILE;

    if (tid == 0) {
#pragma unroll
        for (int s = 0; s < NSTAGE; s++) {
            MBARRIER_INIT(sbase + SM_MBAR + s * 16,     8);   // full[s]: 8 producer warps
            MBARRIER_INIT(sbase + SM_MBAR + s * 16 + 8, 8);   // empty[s]: 8 consumer warps
        }
    }
    if (tid < EXPERTS) ((float*)(smem + SM_SCALES))[tid] = scales[tid];
    __syncthreads();

    if (wid < 8) {
        // ================= PRODUCER (warps 0-7) =================
        // A: warp w stages rows 16w..16w+15. LDG j covers ONE row's 512B fp32
        //    chunk (lane lid -> 16B piece): perfectly coalesced, 4 lines/LDG.
        //    fp16 out: lane lid holds k [4*lid, 4*lid+3] -> sub-row 2r+(lid>>4),
        //    byte (lid&15)*8.
        const float* xA = x + (size_t)(m0 + 16 * wid) * HIDDEN + lid * 4;
        const uint32_t oA0 = (uint32_t)(2 * 16 * wid + (lid >> 4)) * 128 + (lid & 15) * 8;
        // B: thread t (0..255) -> expert e=t>>2, 64B quarter p=t&3 (k [32p,32p+31])
        //    fp16 dst: sub-row 2e+(p>>1), byte (p&1)*64.
        const int e = tid >> 2, p = tid & 3;
        const __half* wpB = g_wh + (size_t)e * HIDDEN + p * 32;
        const uint32_t oB = (uint32_t)(2 * e + (p >> 1)) * 128 + (p & 1) * 64;

        // 1-deep register prefetch (distance = one full iteration >> DRAM latency)
        float4 a[16]; uint4 b[4];
#pragma unroll
        for (int j = 0; j < 16; j++)
            a[j] = *(const float4*)(xA + (size_t)j * HIDDEN);
        {
            const uint4* pb = (const uint4*)wpB;
            b[0] = pb[0]; b[1] = pb[1]; b[2] = pb[2]; b[3] = pb[3];
        }

        int ps = 0, pph = 1;
#pragma unroll 1
        for (int i = 0; i < NITER; i++) {
            MBARRIER_WAIT_PARITY(sbase + SM_MBAR + ps * 16 + 8, pph);
            const uint32_t stg = sbase + SM_STG + ps * STG_BYTES;
#pragma unroll
            for (int j = 0; j < 16; j++) {
                float4 f = a[j];
                uint32_t h0 = pack_f16(f.x, f.y);
                uint32_t h1 = pack_f16(f.z, f.w);
                sts64(stg + SW(oA0 + (uint32_t)j * 256), h0, h1);
            }
            sts128(stg + B_OFF + SW(oB),      b[0].x, b[0].y, b[0].z, b[0].w);
            sts128(stg + B_OFF + SW(oB + 16), b[1].x, b[1].y, b[1].z, b[1].w);
            sts128(stg + B_OFF + SW(oB + 32), b[2].x, b[2].y, b[2].z, b[2].w);
            sts128(stg + B_OFF + SW(oB + 48), b[3].x, b[3].y, b[3].z, b[3].w);
            __syncwarp();
            if (lid == 0) MBARRIER_ARRIVE(sbase + SM_MBAR + ps * 16);
            if (++ps == NSTAGE) { ps = 0; pph ^= 1; }
            if (i + 1 < NITER) {
#pragma unroll
                for (int j = 0; j < 16; j++)
                    a[j] = *(const float4*)(xA + (size_t)j * HIDDEN + (i + 1) * KC);
                const uint4* pb = (const uint4*)(wpB + (i + 1) * KC);
                b[0] = pb[0]; b[1] = pb[1]; b[2] = pb[2]; b[3] = pb[3];
            }
        }
        __syncthreads();  // pairs with consumer fold sync
        __syncthreads();
    } else {
        // ================= CONSUMER (warps 8-15) =================
        // 8 warps = 4 row-groups x 2 k-half groups; warp = 32 rows x 64 experts
        // x 64-k half (4 k-steps of 16). Sub-row = 2*row + kg.
        const int cw = wid - 8;
        const int rg = cw & 3;
        const int kg = cw >> 2;

        uint32_t aBase[2], bBase[4];
#pragma unroll
        for (int mt = 0; mt < 2; mt++)
            aBase[mt] = (uint32_t)(2 * (32 * rg + 16 * mt + (lid & 15)) + kg) * 128
                      + (uint32_t)(lid >> 4) * 16;
#pragma unroll
        for (int nt = 0; nt < 4; nt++)
            bBase[nt] = (uint32_t)(2 * (16 * nt + (lid & 7) + ((lid >> 4) << 3)) + kg) * 128
                      + (uint32_t)((lid >> 3) & 1) * 16;

        float acc[2][8][4];
#pragma unroll
        for (int mt = 0; mt < 2; mt++)
#pragma unroll
            for (int nt = 0; nt < 8; nt++)
#pragma unroll
                for (int j = 0; j < 4; j++) acc[mt][nt][j] = 0.0f;

        int cs = 0, cph = 0;
#pragma unroll 1
        for (int i = 0; i < NITER; i++) {
            MBARRIER_WAIT_PARITY(sbase + SM_MBAR + cs * 16, cph);
            const uint32_t stg = sbase + SM_STG + cs * STG_BYTES;
            const uint32_t AH = stg, BB = stg + B_OFF;
#pragma unroll
            for (int ksl = 0; ksl < 4; ksl++) {
                uint32_t ah[2][4];
                ldsm4(ah[0], AH + SW(aBase[0] + (uint32_t)ksl * 32));
                ldsm4(ah[1], AH + SW(aBase[1] + (uint32_t)ksl * 32));
#pragma unroll
                for (int nt = 0; nt < 4; nt++) {
                    uint32_t bb[4];
                    ldsm4(bb, BB + SW(bBase[nt] + (uint32_t)ksl * 32));
#pragma unroll
                    for (int mt = 0; mt < 2; mt++) {
                        mma16816(acc[mt][2 * nt],     ah[mt], bb[0], bb[1]);
                        mma16816(acc[mt][2 * nt + 1], ah[mt], bb[2], bb[3]);
                    }
                }
            }
            __syncwarp();
            if (lid == 0) MBARRIER_ARRIVE(sbase + SM_MBAR + cs * 16 + 8);
            if (++cs == NSTAGE) { cs = 0; cph ^= 1; }
        }

        // ---- k-half fold: kg=1 dumps, kg=0 adds + writes
        const uint32_t redW = sbase + SM_RED + (uint32_t)rg * 8192;
        if (kg == 1) {
#pragma unroll
            for (int mt = 0; mt < 2; mt++)
#pragma unroll
                for (int nt = 0; nt < 8; nt++)
                    sts128(redW + (uint32_t)(mt * 8 + nt) * 512 + (uint32_t)lid * 16,
                           __float_as_uint(acc[mt][nt][0]), __float_as_uint(acc[mt][nt][1]),
                           __float_as_uint(acc[mt][nt][2]), __float_as_uint(acc[mt][nt][3]));
        }
        __syncthreads();
        if (kg == 0) {
            const float* sc = (const float*)(smem + SM_SCALES);
            const int cq = 2 * (lid & 3);
#pragma unroll
            for (int mt = 0; mt < 2; mt++) {
                const int rbase = m0 + 32 * rg + 16 * mt + (lid >> 2);
#pragma unroll
                for (int nt = 0; nt < 8; nt++) {
                    float u[4];
                    lds128f(u, redW + (uint32_t)(mt * 8 + nt) * 512 + (uint32_t)lid * 16);
                    const int c0 = 8 * nt + cq;
                    const float s0 = sc[c0], s1 = sc[c0 + 1];
                    float2 v0 = make_float2((acc[mt][nt][0] + u[0]) * s0,
                                            (acc[mt][nt][1] + u[1]) * s1);
                    float2 v1 = make_float2((acc[mt][nt][2] + u[2]) * s0,
                                            (acc[mt][nt][3] + u[3]) * s1);
                    *(float2*)(out + (size_t)rbase * EXPERTS + c0)       = v0;
                    *(float2*)(out + (size_t)(rbase + 8) * EXPERTS + c0) = v1;
                }
            }
        }
        __syncthreads();
    }
}

extern "C" void kernel_launch(void* const* d_in, const int* in_sizes, int n_in,
                              void* d_out, int out_size) {
    const float* x      = (const float*)d_in[0];
    const int*   w      = (const int*)d_in[1];
    const float* scales = (const float*)d_in[2];
    float* out = (float*)d_out;

    cudaFuncSetAttribute(gemm_kernel, cudaFuncAttributeMaxDynamicSharedMemorySize, SM_TOTAL);

    dequant_kernel<<<256, 256>>>(w);                 // int32 weights -> fp16 (exact), once
    gemm_kernel<<<NCTAS, NTHREADS, SM_TOTAL>>>(x, scales, out);
}